// round 7
// baseline (speedup 1.0000x reference)
#include <cuda_runtime.h>
#include <cstdint>
#include <cstddef>

#define TT 2048
#define BB 32
#define HH 256
#define NCELL (TT * 2)
#define NCTA 128          // 16 clusters x 8 CTAs

// ---------------- global scratch (allocation-free) ------------------------------
__device__ float g_gi[(size_t)TT * BB * 3 * HH];   // x @ w_ih^T + b_ih  [T][B][768]

// ---------------- helpers ---------------------------------------------------------
__device__ __forceinline__ uint32_t smem_u32(const void* p) {
  uint32_t a;
  asm("{ .reg .u64 t; cvta.to.shared.u64 t, %1; cvt.u32.u64 %0, t; }"
      : "=r"(a) : "l"(p));
  return a;
}
__device__ __forceinline__ uint64_t pack2(float a, float b) {
  uint64_t r;
  asm("mov.b64 %0, {%1, %2};" : "=l"(r) : "f"(a), "f"(b));
  return r;
}
__device__ __forceinline__ void unpack2(float& a, float& b, uint64_t v) {
  asm("mov.b64 {%0, %1}, %2;" : "=f"(a), "=f"(b) : "l"(v));
}
__device__ __forceinline__ void fma2(uint64_t& d, uint64_t a, uint64_t b) {
  asm("fma.rn.f32x2 %0, %1, %2, %0;" : "+l"(d) : "l"(a), "l"(b));
}
__device__ __forceinline__ float hadd(uint64_t v) {
  float a, b;
  unpack2(a, b, v);
  return a + b;
}

__device__ __forceinline__ void mbar_init(uint32_t addr, uint32_t cnt) {
  asm volatile("mbarrier.init.shared.b64 [%0], %1;" :: "r"(addr), "r"(cnt) : "memory");
}
// wait with cluster-scope acquire (peers' DSMEM writes must be visible)
__device__ __forceinline__ void mbar_wait_cluster(uint32_t addr, uint32_t parity) {
  asm volatile(
      "{\n\t.reg .pred P;\n\t"
      "WL_%=:\n\t"
      "mbarrier.try_wait.parity.acquire.cluster.shared::cta.b64 P, [%0], %1, 0x989680;\n\t"
      "@P bra.uni WD_%=;\n\t"
      "bra.uni WL_%=;\n\t"
      "WD_%=:\n\t}"
      :: "r"(addr), "r"(parity) : "memory");
}
__device__ __forceinline__ void st_cluster_f32(uint32_t local_addr, uint32_t rank, float v) {
  asm volatile(
      "{\n\t.reg .b32 ra;\n\t"
      "mapa.shared::cluster.u32 ra, %0, %1;\n\t"
      "st.shared::cluster.f32 [ra], %2;\n\t}"
      :: "r"(local_addr), "r"(rank), "f"(v) : "memory");
}
__device__ __forceinline__ void arrive_cluster(uint32_t local_mbar, uint32_t rank) {
  asm volatile(
      "{\n\t.reg .b32 ra;\n\t"
      "mapa.shared::cluster.u32 ra, %0, %1;\n\t"
      "mbarrier.arrive.release.cluster.shared::cluster.b64 _, [ra];\n\t}"
      :: "r"(local_mbar), "r"(rank) : "memory");
}
#define CLUSTER_SYNC_()                                              \
  do {                                                               \
    asm volatile("barrier.cluster.arrive.aligned;" ::: "memory");    \
    asm volatile("barrier.cluster.wait.aligned;" ::: "memory");      \
  } while (0)

// ---------------- gi precompute (f32x2 packed over k-pairs) -----------------------
__global__ __launch_bounds__(256) void gi_kernel(
    const float* __restrict__ x, const float* __restrict__ w_ih,
    const float* __restrict__ b_ih) {
  __shared__ float xs[32 * 260];
  __shared__ float ws[128 * 18];
  const int t   = blockIdx.x;
  const int gc0 = blockIdx.y * 128;
  const int tid = threadIdx.x;

  for (int i = tid; i < 2048; i += 256) {
    int b = i >> 6;
    int c4 = (i & 63) << 2;
    float4 v = *(const float4*)(x + ((size_t)b * TT + t) * HH + c4);
    *(float4*)(xs + b * 260 + c4) = v;
  }

  const int bq = tid >> 5;
  const int gq = tid & 31;

  uint64_t acc2[4][4];
#pragma unroll
  for (int i = 0; i < 4; i++)
#pragma unroll
    for (int j = 0; j < 4; j++) acc2[i][j] = pack2(0.f, 0.f);

  for (int kt = 0; kt < 16; ++kt) {
    const int k0 = kt * 16;
    __syncthreads();
    for (int i = tid; i < 1024; i += 256) {
      int r = i >> 3;
      int c2 = (i & 7) << 1;
      *(float2*)(ws + r * 18 + c2) =
          *(const float2*)(w_ih + (size_t)(gc0 + r) * HH + k0 + c2);
    }
    __syncthreads();
#pragma unroll
    for (int kp = 0; kp < 8; ++kp) {
      const int kk = kp << 1;
      uint64_t w2[4];
#pragma unroll
      for (int j = 0; j < 4; j++)
        w2[j] = *(const uint64_t*)(ws + (gq + 32 * j) * 18 + kk);
#pragma unroll
      for (int i = 0; i < 4; i++) {
        const uint64_t x2 = *(const uint64_t*)(xs + (bq * 4 + i) * 260 + k0 + kk);
#pragma unroll
        for (int j = 0; j < 4; j++) fma2(acc2[i][j], x2, w2[j]);
      }
    }
  }
#pragma unroll
  for (int j = 0; j < 4; j++) {
    int g = gc0 + gq + 32 * j;
    float bias = b_ih[g];
#pragma unroll
    for (int i = 0; i < 4; i++) {
      float a, b;
      unpack2(a, b, acc2[i][j]);
      g_gi[((size_t)t * BB + (bq * 4 + i)) * 768 + g] = a + b + bias;
    }
  }
}

// ---------------- clustered recurrent scan ----------------------------------------
// Cluster (8 CTAs) owns 2 batch elements; CTA rank r owns h columns [32r,32r+32).
// Weights (96 rows x 256) live in registers as K-paired f32x2. h circulates via
// DSMEM stores + mbarrier full[2] (count 8, one arrive per CTA per cell).
__global__ __launch_bounds__(256, 1) __cluster_dims__(8, 1, 1)
void scan_kernel(const float* __restrict__ hidden, const float* __restrict__ w_hh,
                 const float* __restrict__ b_hh, float* __restrict__ out) {
  __shared__ float bufs[2][2][HH];          // [parity][local batch][col]
  __shared__ float part[256 * 6];           // [kq*32+rl][g*2+b]
  __shared__ __align__(8) unsigned long long mbar[2];

  const int tid  = threadIdx.x;
  const int rank = blockIdx.x & 7;
  const int cid  = blockIdx.x >> 3;
  const int kq   = tid >> 5;                // K-slice [kq*32, kq*32+32)
  const int rl   = tid & 31;                // local column
  const int co   = rank * 32;
  const int b0   = cid * 2;                 // global batch base

  const uint32_t mb0 = smem_u32(&mbar[0]);
  const uint32_t mb1 = smem_u32(&mbar[1]);

  // ---- persistent weights: K-paired packed, 48 x u64 regs ----
  uint64_t w2[3][16];
#pragma unroll
  for (int g = 0; g < 3; ++g) {
    const uint64_t* wp =
        (const uint64_t*)(w_hh + (size_t)(g * HH + co + rl) * HH + kq * 32);
#pragma unroll
    for (int kp = 0; kp < 16; ++kp) w2[g][kp] = wp[kp];
  }

  // epilogue-thread registers (tid < 64): thread e -> (erl = e>>1, eb = e&1)
  const int erl = tid >> 1, eb = tid & 1;
  float br = 0.f, bz = 0.f, bn = 0.f;
  if (tid < 64) {
    br = b_hh[0 * HH + co + erl];
    bz = b_hh[1 * HH + co + erl];
    bn = b_hh[2 * HH + co + erl];
  }

  if (tid == 0) {
    mbar_init(mb0, 8);
    mbar_init(mb1, 8);
  }
  // initial h into bufs[0]
  for (int i = tid; i < 2 * HH; i += 256)
    bufs[0][i >> 8][i & 255] = hidden[(size_t)(b0 + (i >> 8)) * HH + (i & 255)];
  __syncthreads();
  CLUSTER_SYNC_();   // mbarrier inits + initial h visible cluster-wide

  for (int cell = 0; cell < NCELL; ++cell) {
    if (cell > 0) {
      const uint32_t par = (uint32_t)(((cell - 1) >> 1) & 1);
      mbar_wait_cluster((cell & 1) ? mb1 : mb0, par);
    }
    const float* hb = &bufs[cell & 1][0][0];

    // gi prefetch for epilogue threads (latency hidden behind compute)
    float gir = 0.f, giz = 0.f, gin = 0.f;
    if (tid < 64) {
      const float* gp =
          g_gi + ((size_t)(cell >> 1) * BB + b0 + eb) * 768 + co + erl;
      gir = gp[0];
      giz = gp[256];
      gin = gp[512];
    }

    // ---- compute: 96 fma2 per thread, h via broadcast LDS.64 ----
    uint64_t aR0 = pack2(0.f, 0.f), aR1 = aR0, aZ0 = aR0, aZ1 = aR0,
             aN0 = aR0, aN1 = aR0;
    const uint64_t* h0p = (const uint64_t*)(hb + kq * 32);
    const uint64_t* h1p = (const uint64_t*)(hb + HH + kq * 32);
#pragma unroll
    for (int kp = 0; kp < 16; ++kp) {
      const uint64_t h0 = h0p[kp];
      const uint64_t h1 = h1p[kp];
      fma2(aR0, w2[0][kp], h0);
      fma2(aR1, w2[0][kp], h1);
      fma2(aZ0, w2[1][kp], h0);
      fma2(aZ1, w2[1][kp], h1);
      fma2(aN0, w2[2][kp], h0);
      fma2(aN1, w2[2][kp], h1);
    }
    {
      float* mp = part + (kq * 32 + rl) * 6;
      mp[0] = hadd(aR0);
      mp[1] = hadd(aR1);
      mp[2] = hadd(aZ0);
      mp[3] = hadd(aZ1);
      mp[4] = hadd(aN0);
      mp[5] = hadd(aN1);
    }
    __syncthreads();

    // ---- epilogue (tid < 64): reduce over kq, gates, DSMEM broadcast ----
    if (tid < 64) {
      float sr = br, sz = bz, sn = bn;
#pragma unroll
      for (int k2 = 0; k2 < 8; ++k2) {
        const float* p = part + (k2 * 32 + erl) * 6 + eb;
        sr += p[0];
        sz += p[2];
        sn += p[4];
      }
      const float r = 1.f / (1.f + expf(-(gir + sr)));
      const float z = 1.f / (1.f + expf(-(giz + sz)));
      const float n = tanhf(gin + r * sn);
      const float hold = hb[eb * HH + co + erl];
      const float hn = (1.f - z) * n + z * hold;

      if (cell + 1 < NCELL) {
        const uint32_t dst =
            smem_u32(&bufs[(cell + 1) & 1][eb][co + erl]);
#pragma unroll
        for (int r8 = 0; r8 < 8; ++r8) st_cluster_f32(dst, (uint32_t)r8, hn);
        asm volatile("bar.sync 1, 64;" ::: "memory");
        if (tid == 0) {
          asm volatile("fence.acq_rel.cluster;" ::: "memory");
          const uint32_t mb = ((cell + 1) & 1) ? mb1 : mb0;
#pragma unroll
          for (int r8 = 0; r8 < 8; ++r8) arrive_cluster(mb, (uint32_t)r8);
        }
      }
      if (cell & 1)
        out[((size_t)(cell >> 1) * BB + b0 + eb) * HH + co + erl] = hn;
    }
  }
  CLUSTER_SYNC_();   // no CTA exits while peers may still touch its SMEM
}

// ---------------- launch ----------------------------------------------------------
extern "C" void kernel_launch(void* const* d_in, const int* in_sizes, int n_in,
                              void* d_out, int out_size) {
  const float *input = 0, *hidden = 0, *w_ih = 0, *w_hh = 0, *b_ih = 0, *b_hh = 0;
  for (int i = 0; i < n_in; ++i) {
    long s = in_sizes[i];
    if (s == (long)BB * TT * HH) {
      input = (const float*)d_in[i];
    } else if (s == BB * HH && !hidden) {
      hidden = (const float*)d_in[i];
    } else if (s == 3 * HH * HH) {
      if (!w_ih) w_ih = (const float*)d_in[i]; else w_hh = (const float*)d_in[i];
    } else if (s == 3 * HH) {
      if (!b_ih) b_ih = (const float*)d_in[i]; else b_hh = (const float*)d_in[i];
    }
  }
  gi_kernel<<<dim3(TT, 6), 256>>>(input, w_ih, b_ih);
  scan_kernel<<<NCTA, 256>>>(hidden, w_hh, b_hh, (float*)d_out);
}

// round 8
// speedup vs baseline: 1.8175x; 1.8175x over previous
#include <cuda_runtime.h>
#include <cstdint>
#include <cstddef>

#define TT 2048
#define BB 32
#define HH 256
#define NCELL (TT * 2)
#define NCTA 128          // 16 clusters x 8 CTAs

// ---------------- global scratch (allocation-free) ------------------------------
__device__ float g_gi[(size_t)TT * BB * 3 * HH];   // x @ w_ih^T + b_ih  [T][B][768]

// ---------------- helpers ---------------------------------------------------------
__device__ __forceinline__ uint32_t smem_u32(const void* p) {
  uint32_t a;
  asm("{ .reg .u64 t; cvta.to.shared.u64 t, %1; cvt.u32.u64 %0, t; }"
      : "=r"(a) : "l"(p));
  return a;
}
__device__ __forceinline__ uint64_t pack2(float a, float b) {
  uint64_t r;
  asm("mov.b64 %0, {%1, %2};" : "=l"(r) : "f"(a), "f"(b));
  return r;
}
__device__ __forceinline__ void unpack2(float& a, float& b, uint64_t v) {
  asm("mov.b64 {%0, %1}, %2;" : "=f"(a), "=f"(b) : "l"(v));
}
__device__ __forceinline__ void fma2(uint64_t& d, uint64_t a, uint64_t b) {
  asm("fma.rn.f32x2 %0, %1, %2, %0;" : "+l"(d) : "l"(a), "l"(b));
}
__device__ __forceinline__ float hadd(uint64_t v) {
  float a, b;
  unpack2(a, b, v);
  return a + b;
}
// store (value,seq) u64 into CTA `rank`'s SMEM at this CTA's local offset
__device__ __forceinline__ void st_cluster_u64(uint32_t local_addr, uint32_t rank,
                                               uint64_t v) {
  asm volatile(
      "{\n\t.reg .b32 ra;\n\t"
      "mapa.shared::cluster.u32 ra, %0, %1;\n\t"
      "st.relaxed.cluster.shared::cluster.u64 [ra], %2;\n\t}"
      :: "r"(local_addr), "r"(rank), "l"(v) : "memory");
}
// volatile 2x u64 poll load from local SMEM
__device__ __forceinline__ void ld_pair_vol(uint32_t addr, uint64_t& a, uint64_t& b) {
  asm volatile("ld.volatile.shared.v2.u64 {%0, %1}, [%2];"
               : "=l"(a), "=l"(b) : "r"(addr) : "memory");
}
#define CLUSTER_SYNC_()                                              \
  do {                                                               \
    asm volatile("barrier.cluster.arrive.aligned;" ::: "memory");    \
    asm volatile("barrier.cluster.wait.aligned;" ::: "memory");      \
  } while (0)

// ---------------- gi precompute (f32x2 packed over k-pairs) -----------------------
__global__ __launch_bounds__(256) void gi_kernel(
    const float* __restrict__ x, const float* __restrict__ w_ih,
    const float* __restrict__ b_ih) {
  __shared__ float xs[32 * 260];
  __shared__ float ws[128 * 18];
  const int t   = blockIdx.x;
  const int gc0 = blockIdx.y * 128;
  const int tid = threadIdx.x;

  for (int i = tid; i < 2048; i += 256) {
    int b = i >> 6;
    int c4 = (i & 63) << 2;
    float4 v = *(const float4*)(x + ((size_t)b * TT + t) * HH + c4);
    *(float4*)(xs + b * 260 + c4) = v;
  }

  const int bq = tid >> 5;
  const int gq = tid & 31;

  uint64_t acc2[4][4];
#pragma unroll
  for (int i = 0; i < 4; i++)
#pragma unroll
    for (int j = 0; j < 4; j++) acc2[i][j] = pack2(0.f, 0.f);

  for (int kt = 0; kt < 16; ++kt) {
    const int k0 = kt * 16;
    __syncthreads();
    for (int i = tid; i < 1024; i += 256) {
      int r = i >> 3;
      int c2 = (i & 7) << 1;
      *(float2*)(ws + r * 18 + c2) =
          *(const float2*)(w_ih + (size_t)(gc0 + r) * HH + k0 + c2);
    }
    __syncthreads();
#pragma unroll
    for (int kp = 0; kp < 8; ++kp) {
      const int kk = kp << 1;
      uint64_t w2[4];
#pragma unroll
      for (int j = 0; j < 4; j++)
        w2[j] = *(const uint64_t*)(ws + (gq + 32 * j) * 18 + kk);
#pragma unroll
      for (int i = 0; i < 4; i++) {
        const uint64_t x2 = *(const uint64_t*)(xs + (bq * 4 + i) * 260 + k0 + kk);
#pragma unroll
        for (int j = 0; j < 4; j++) fma2(acc2[i][j], x2, w2[j]);
      }
    }
  }
#pragma unroll
  for (int j = 0; j < 4; j++) {
    int g = gc0 + gq + 32 * j;
    float bias = b_ih[g];
#pragma unroll
    for (int i = 0; i < 4; i++) {
      float a, b;
      unpack2(a, b, acc2[i][j]);
      g_gi[((size_t)t * BB + (bq * 4 + i)) * 768 + g] = a + b + bias;
    }
  }
}

// ---------------- clustered recurrent scan (payload-seq DSMEM sync) ---------------
// Cluster (8 CTAs) owns 2 batches; CTA rank owns 32 h-cols; weights in 48 u64 regs.
// Publish: one relaxed DSMEM u64 (value,seq) per peer. Consume: poll OWN SMEM.
// No mbarriers, no fences, no arrives in the loop; one __syncthreads per cell.
__global__ __launch_bounds__(256, 1) __cluster_dims__(8, 1, 1)
void scan_kernel(const float* __restrict__ hidden, const float* __restrict__ w_hh,
                 const float* __restrict__ b_hh, float* __restrict__ out) {
  __shared__ __align__(16) unsigned long long bufs[2][2][HH];  // [parity][b][col]
  __shared__ __align__(16) float hT[2][HH];                    // compacted h values

  const int tid  = threadIdx.x;
  const int rank = blockIdx.x & 7;
  const int cid  = blockIdx.x >> 3;
  const int warp = tid >> 5;
  const int lane = tid & 31;
  const int kq   = lane >> 2;          // K-slice [kq*32, kq*32+32) ; lane bits 2..4
  const int jl   = lane & 3;           // col within warp group
  const int colL = warp * 4 + jl;      // 0..31
  const int col  = rank * 32 + colL;   // global column
  const int b0   = cid * 2;            // global batch base

  // ---- persistent weights: thread's 3 gate rows x 32 k, K-paired (48 u64) ----
  uint64_t w2[3][16];
#pragma unroll
  for (int g = 0; g < 3; ++g) {
    const uint64_t* wp =
        (const uint64_t*)(w_hh + (size_t)(g * HH + col) * HH + kq * 32);
#pragma unroll
    for (int kp = 0; kp < 16; ++kp) w2[g][kp] = wp[kp];
  }
  // biases for epilogue lanes (kq<2)
  float br = 0.f, bz = 0.f, bn = 0.f;
  if (kq < 2) {
    br = b_hh[0 * HH + col];
    bz = b_hh[1 * HH + col];
    bn = b_hh[2 * HH + col];
  }

  // ---- init: zero seq buffers; initial h into hT ----
  for (int i = tid; i < 2 * 2 * HH; i += 256) ((unsigned long long*)bufs)[i] = 0ull;
  for (int i = tid; i < 2 * HH; i += 256)
    hT[i >> 8][i & 255] = hidden[(size_t)(b0 + (i >> 8)) * HH + (i & 255)];
  __syncthreads();
  CLUSTER_SYNC_();   // zeroed bufs visible before any peer publishes

  const int pi = tid * 2;                   // this thread's 2 (b,col) pairs
  const int pb = pi >> 8, pc = pi & 255;
  const uint32_t pollA = smem_u32(&bufs[0][0][0]) + (uint32_t)pi * 8u;
  const uint32_t pollB = pollA + 2u * HH * 8u;

  for (int cell = 0; cell < NCELL; ++cell) {
    // ---- poll own SMEM for this cell's h; compact into hT ----
    if (cell > 0) {
      const uint32_t pa = (cell & 1) ? pollB : pollA;
      const uint32_t tgt = (uint32_t)cell;
      uint64_t v0, v1;
      ld_pair_vol(pa, v0, v1);
      while ((uint32_t)(v0 >> 32) != tgt || (uint32_t)(v1 >> 32) != tgt)
        ld_pair_vol(pa, v0, v1);
      *(float2*)&hT[pb][pc] =
          make_float2(__uint_as_float((uint32_t)v0), __uint_as_float((uint32_t)v1));
      __syncthreads();
    }
    // gi prefetch for epilogue lanes (L2 latency hidden behind FMA)
    float gir = 0.f, giz = 0.f, gin = 0.f;
    if (kq < 2) {
      const float* gp =
          g_gi + ((size_t)(cell >> 1) * BB + b0 + kq) * 768 + col;
      gir = __ldg(gp);
      giz = __ldg(gp + 256);
      gin = __ldg(gp + 512);
    }

    // ---- FMA: 96 fma2 over this thread's (col, K-slice), both batches ----
    uint64_t aR0 = pack2(0.f, 0.f), aR1 = aR0, aZ0 = aR0, aZ1 = aR0,
             aN0 = aR0, aN1 = aR0;
    const uint64_t* H0 = (const uint64_t*)(&hT[0][kq * 32]);
    const uint64_t* H1 = (const uint64_t*)(&hT[1][kq * 32]);
#pragma unroll
    for (int kp = 0; kp < 16; ++kp) {
      const uint64_t h0 = H0[kp];
      const uint64_t h1 = H1[kp];
      fma2(aR0, w2[0][kp], h0);
      fma2(aR1, w2[0][kp], h1);
      fma2(aZ0, w2[1][kp], h0);
      fma2(aZ1, w2[1][kp], h1);
      fma2(aN0, w2[2][kp], h0);
      fma2(aN1, w2[2][kp], h1);
    }
    float sR0 = hadd(aR0), sR1 = hadd(aR1), sZ0 = hadd(aZ0), sZ1 = hadd(aZ1),
          sN0 = hadd(aN0), sN1 = hadd(aN1);
    // butterfly over kq (lane bits 2..4): every lane gets full dot products
#pragma unroll
    for (int m = 4; m <= 16; m <<= 1) {
      sR0 += __shfl_xor_sync(0xffffffffu, sR0, m);
      sR1 += __shfl_xor_sync(0xffffffffu, sR1, m);
      sZ0 += __shfl_xor_sync(0xffffffffu, sZ0, m);
      sZ1 += __shfl_xor_sync(0xffffffffu, sZ1, m);
      sN0 += __shfl_xor_sync(0xffffffffu, sN0, m);
      sN1 += __shfl_xor_sync(0xffffffffu, sN1, m);
    }

    // ---- epilogue lanes: kq==0 -> batch 0, kq==1 -> batch 1 ----
    if (kq < 2) {
      const float sr = (kq == 0) ? sR0 : sR1;
      const float sz = (kq == 0) ? sZ0 : sZ1;
      const float sn = (kq == 0) ? sN0 : sN1;
      const float r = 1.f / (1.f + expf(-(gir + sr + br)));
      const float z = 1.f / (1.f + expf(-(giz + sz + bz)));
      const float n = tanhf(gin + r * (sn + bn));
      const float hold = hT[kq][col];
      const float hn = (1.f - z) * n + z * hold;
      if (cell + 1 < NCELL) {
        const uint64_t pkd =
            ((uint64_t)(uint32_t)(cell + 1) << 32) | (uint64_t)__float_as_uint(hn);
        const uint32_t dst = smem_u32(&bufs[(cell + 1) & 1][kq][col]);
#pragma unroll
        for (int r8 = 0; r8 < 8; ++r8) st_cluster_u64(dst, (uint32_t)r8, pkd);
      }
      if (cell & 1)
        out[((size_t)(cell >> 1) * BB + b0 + kq) * HH + col] = hn;
    }
  }
  CLUSTER_SYNC_();   // no CTA exits while peers may still store into its SMEM
}

// ---------------- launch ----------------------------------------------------------
extern "C" void kernel_launch(void* const* d_in, const int* in_sizes, int n_in,
                              void* d_out, int out_size) {
  const float *input = 0, *hidden = 0, *w_ih = 0, *w_hh = 0, *b_ih = 0, *b_hh = 0;
  for (int i = 0; i < n_in; ++i) {
    long s = in_sizes[i];
    if (s == (long)BB * TT * HH) {
      input = (const float*)d_in[i];
    } else if (s == BB * HH && !hidden) {
      hidden = (const float*)d_in[i];
    } else if (s == 3 * HH * HH) {
      if (!w_ih) w_ih = (const float*)d_in[i]; else w_hh = (const float*)d_in[i];
    } else if (s == 3 * HH) {
      if (!b_ih) b_ih = (const float*)d_in[i]; else b_hh = (const float*)d_in[i];
    }
  }
  gi_kernel<<<dim3(TT, 6), 256>>>(input, w_ih, b_ih);
  scan_kernel<<<NCTA, 256>>>(hidden, w_hh, b_hh, (float*)d_out);
}

// round 9
// speedup vs baseline: 1.9541x; 1.0752x over previous
#include <cuda_runtime.h>
#include <cstdint>
#include <cstddef>

#define TT 2048
#define BB 32
#define HH 256
#define NCELL (TT * 2)
#define NCTA 128          // 16 clusters x 8 CTAs

// ---------------- global scratch (allocation-free) ------------------------------
__device__ float g_gi[(size_t)TT * BB * 3 * HH];   // x @ w_ih^T + b_ih  [T][B][768]

// ---------------- helpers ---------------------------------------------------------
__device__ __forceinline__ uint32_t smem_u32(const void* p) {
  uint32_t a;
  asm("{ .reg .u64 t; cvta.to.shared.u64 t, %1; cvt.u32.u64 %0, t; }"
      : "=r"(a) : "l"(p));
  return a;
}
__device__ __forceinline__ uint64_t pack2(float a, float b) {
  uint64_t r;
  asm("mov.b64 %0, {%1, %2};" : "=l"(r) : "f"(a), "f"(b));
  return r;
}
__device__ __forceinline__ void unpack2(float& a, float& b, uint64_t v) {
  asm("mov.b64 {%0, %1}, %2;" : "=f"(a), "=f"(b) : "l"(v));
}
__device__ __forceinline__ void fma2(uint64_t& d, uint64_t a, uint64_t b) {
  asm("fma.rn.f32x2 %0, %1, %2, %0;" : "+l"(d) : "l"(a), "l"(b));
}
__device__ __forceinline__ float hadd(uint64_t v) {
  float a, b;
  unpack2(a, b, v);
  return a + b;
}
// store (value,seq) u64 into CTA `rank`'s SMEM at this CTA's local offset
__device__ __forceinline__ void st_cluster_u64(uint32_t local_addr, uint32_t rank,
                                               uint64_t v) {
  asm volatile(
      "{\n\t.reg .b32 ra;\n\t"
      "mapa.shared::cluster.u32 ra, %0, %1;\n\t"
      "st.relaxed.cluster.shared::cluster.u64 [ra], %2;\n\t}"
      :: "r"(local_addr), "r"(rank), "l"(v) : "memory");
}
// volatile 2x u64 poll load from local SMEM
__device__ __forceinline__ void ld_pair_vol(uint32_t addr, uint64_t& a, uint64_t& b) {
  asm volatile("ld.volatile.shared.v2.u64 {%0, %1}, [%2];"
               : "=l"(a), "=l"(b) : "r"(addr) : "memory");
}
#define CLUSTER_SYNC_()                                              \
  do {                                                               \
    asm volatile("barrier.cluster.arrive.aligned;" ::: "memory");    \
    asm volatile("barrier.cluster.wait.aligned;" ::: "memory");      \
  } while (0)

// ---------------- gi precompute (f32x2 packed over k-pairs) -----------------------
__global__ __launch_bounds__(256) void gi_kernel(
    const float* __restrict__ x, const float* __restrict__ w_ih,
    const float* __restrict__ b_ih) {
  __shared__ float xs[32 * 260];
  __shared__ float ws[128 * 18];
  const int t   = blockIdx.x;
  const int gc0 = blockIdx.y * 128;
  const int tid = threadIdx.x;

  for (int i = tid; i < 2048; i += 256) {
    int b = i >> 6;
    int c4 = (i & 63) << 2;
    float4 v = *(const float4*)(x + ((size_t)b * TT + t) * HH + c4);
    *(float4*)(xs + b * 260 + c4) = v;
  }

  const int bq = tid >> 5;
  const int gq = tid & 31;

  uint64_t acc2[4][4];
#pragma unroll
  for (int i = 0; i < 4; i++)
#pragma unroll
    for (int j = 0; j < 4; j++) acc2[i][j] = pack2(0.f, 0.f);

  for (int kt = 0; kt < 16; ++kt) {
    const int k0 = kt * 16;
    __syncthreads();
    for (int i = tid; i < 1024; i += 256) {
      int r = i >> 3;
      int c2 = (i & 7) << 1;
      *(float2*)(ws + r * 18 + c2) =
          *(const float2*)(w_ih + (size_t)(gc0 + r) * HH + k0 + c2);
    }
    __syncthreads();
#pragma unroll
    for (int kp = 0; kp < 8; ++kp) {
      const int kk = kp << 1;
      uint64_t w2[4];
#pragma unroll
      for (int j = 0; j < 4; j++)
        w2[j] = *(const uint64_t*)(ws + (gq + 32 * j) * 18 + kk);
#pragma unroll
      for (int i = 0; i < 4; i++) {
        const uint64_t x2 = *(const uint64_t*)(xs + (bq * 4 + i) * 260 + k0 + kk);
#pragma unroll
        for (int j = 0; j < 4; j++) fma2(acc2[i][j], x2, w2[j]);
      }
    }
  }
#pragma unroll
  for (int j = 0; j < 4; j++) {
    int g = gc0 + gq + 32 * j;
    float bias = b_ih[g];
#pragma unroll
    for (int i = 0; i < 4; i++) {
      float a, b;
      unpack2(a, b, acc2[i][j]);
      g_gi[((size_t)t * BB + (bq * 4 + i)) * 768 + g] = a + b + bias;
    }
  }
}

// ---------------- clustered recurrent scan (payload-seq DSMEM sync) ---------------
// Cluster (8 CTAs) owns 2 batches; CTA rank owns 32 h-cols; weights in 48 u64 regs.
// hT padded (34 floats per 32-k slice) -> conflict-free broadcast LDS.64.
// After butterfly ALL lanes hold full sums: each lane serves ONE rank (kq) with
// 2 DSMEM (value,seq) stores. Consumers poll OWN SMEM with nanosleep backoff.
__global__ __launch_bounds__(256, 1) __cluster_dims__(8, 1, 1)
void scan_kernel(const float* __restrict__ hidden, const float* __restrict__ w_hh,
                 const float* __restrict__ b_hh, float* __restrict__ out) {
  __shared__ __align__(16) unsigned long long bufs[2][2][HH];  // [parity][b][col]
  __shared__ __align__(16) float hT[2][8 * 34];                // padded slices

  const int tid  = threadIdx.x;
  const int rank = blockIdx.x & 7;
  const int cid  = blockIdx.x >> 3;
  const int warp = tid >> 5;
  const int lane = tid & 31;
  const int kq   = lane >> 2;          // K-slice [kq*32, kq*32+32); lane bits 2..4
  const int jl   = lane & 3;
  const int colL = warp * 4 + jl;      // 0..31
  const int col  = rank * 32 + colL;   // global column
  const int b0   = cid * 2;            // global batch base

  // ---- persistent weights: thread's 3 gate rows x 32 k, K-paired (48 u64) ----
  uint64_t w2[3][16];
#pragma unroll
  for (int g = 0; g < 3; ++g) {
    const uint64_t* wp =
        (const uint64_t*)(w_hh + (size_t)(g * HH + col) * HH + kq * 32);
#pragma unroll
    for (int kp = 0; kp < 16; ++kp) w2[g][kp] = wp[kp];
  }
  const float br = b_hh[0 * HH + col];
  const float bz = b_hh[1 * HH + col];
  const float bn = b_hh[2 * HH + col];

  // ---- init: zero seq buffers; initial h into hT (padded) ----
  for (int i = tid; i < 2 * 2 * HH; i += 256) ((unsigned long long*)bufs)[i] = 0ull;
  for (int i = tid; i < 2 * HH; i += 256) {
    int b = i >> 8, k = i & 255;
    hT[b][(k >> 5) * 34 + (k & 31)] = hidden[(size_t)(b0 + b) * HH + k];
  }
  __syncthreads();
  CLUSTER_SYNC_();   // zeroed bufs visible before any peer publishes

  const int pi = tid * 2;                   // this thread's 2 consecutive (b,col)
  const int pb = pi >> 8, pc = pi & 255;
  const uint32_t pollA = smem_u32(&bufs[0][0][0]) + (uint32_t)pi * 8u;
  const uint32_t pollB = pollA + 2u * HH * 8u;
  const int hTpos = (pc >> 5) * 34 + (pc & 31);       // padded write position
  const int holdP = rank * 34 + colL;                 // padded own-col position

  for (int cell = 0; cell < NCELL; ++cell) {
    // ---- poll own SMEM for this cell's h; compact into padded hT ----
    if (cell > 0) {
      const uint32_t pa = (cell & 1) ? pollB : pollA;
      const uint32_t tgt = (uint32_t)cell;
      uint64_t v0, v1;
      ld_pair_vol(pa, v0, v1);
      while ((uint32_t)(v0 >> 32) != tgt || (uint32_t)(v1 >> 32) != tgt) {
        __nanosleep(20);
        ld_pair_vol(pa, v0, v1);
      }
      *(float2*)&hT[pb][hTpos] =
          make_float2(__uint_as_float((uint32_t)v0), __uint_as_float((uint32_t)v1));
      __syncthreads();
    }
    // gi prefetch, both batches (L2 latency hidden behind FMA)
    const float* gp = g_gi + ((size_t)(cell >> 1) * BB + b0) * 768 + col;
    const float gir0 = __ldg(gp), giz0 = __ldg(gp + 256), gin0 = __ldg(gp + 512);
    const float gir1 = __ldg(gp + 768), giz1 = __ldg(gp + 1024),
                gin1 = __ldg(gp + 1280);

    // ---- FMA: 96 fma2 over (col, K-slice), both batches; conflict-free LDS ----
    uint64_t aR0 = pack2(0.f, 0.f), aR1 = aR0, aZ0 = aR0, aZ1 = aR0,
             aN0 = aR0, aN1 = aR0;
    const uint64_t* H0 = (const uint64_t*)(&hT[0][kq * 34]);
    const uint64_t* H1 = (const uint64_t*)(&hT[1][kq * 34]);
#pragma unroll
    for (int kp = 0; kp < 16; ++kp) {
      const uint64_t h0 = H0[kp];
      const uint64_t h1 = H1[kp];
      fma2(aR0, w2[0][kp], h0);
      fma2(aR1, w2[0][kp], h1);
      fma2(aZ0, w2[1][kp], h0);
      fma2(aZ1, w2[1][kp], h1);
      fma2(aN0, w2[2][kp], h0);
      fma2(aN1, w2[2][kp], h1);
    }
    float sR0 = hadd(aR0), sR1 = hadd(aR1), sZ0 = hadd(aZ0), sZ1 = hadd(aZ1),
          sN0 = hadd(aN0), sN1 = hadd(aN1);
    // butterfly over kq (lane bits 2..4): every lane ends with full dot products
#pragma unroll
    for (int m = 4; m <= 16; m <<= 1) {
      sR0 += __shfl_xor_sync(0xffffffffu, sR0, m);
      sR1 += __shfl_xor_sync(0xffffffffu, sR1, m);
      sZ0 += __shfl_xor_sync(0xffffffffu, sZ0, m);
      sZ1 += __shfl_xor_sync(0xffffffffu, sZ1, m);
      sN0 += __shfl_xor_sync(0xffffffffu, sN0, m);
      sN1 += __shfl_xor_sync(0xffffffffu, sN1, m);
    }

    // ---- gates in ALL lanes (no extra MUFU cost); each lane serves rank kq ----
    const float r0 = 1.f / (1.f + expf(-(gir0 + sR0 + br)));
    const float z0 = 1.f / (1.f + expf(-(giz0 + sZ0 + bz)));
    const float n0 = tanhf(gin0 + r0 * (sN0 + bn));
    const float hn0 = (1.f - z0) * n0 + z0 * hT[0][holdP];
    const float r1 = 1.f / (1.f + expf(-(gir1 + sR1 + br)));
    const float z1 = 1.f / (1.f + expf(-(giz1 + sZ1 + bz)));
    const float n1 = tanhf(gin1 + r1 * (sN1 + bn));
    const float hn1 = (1.f - z1) * n1 + z1 * hT[1][holdP];

    if (cell + 1 < NCELL) {
      const uint64_t seqHi = (uint64_t)(uint32_t)(cell + 1) << 32;
      const uint32_t dst0 = smem_u32(&bufs[(cell + 1) & 1][0][col]);
      st_cluster_u64(dst0, (uint32_t)kq, seqHi | (uint64_t)__float_as_uint(hn0));
      st_cluster_u64(dst0 + HH * 8u, (uint32_t)kq,
                     seqHi | (uint64_t)__float_as_uint(hn1));
    }
    if (cell & 1) {
      if (kq == 0)
        out[((size_t)(cell >> 1) * BB + b0) * HH + col] = hn0;
      else if (kq == 1)
        out[((size_t)(cell >> 1) * BB + b0 + 1) * HH + col] = hn1;
    }
  }
  CLUSTER_SYNC_();   // no CTA exits while peers may still store into its SMEM
}

// ---------------- launch ----------------------------------------------------------
extern "C" void kernel_launch(void* const* d_in, const int* in_sizes, int n_in,
                              void* d_out, int out_size) {
  const float *input = 0, *hidden = 0, *w_ih = 0, *w_hh = 0, *b_ih = 0, *b_hh = 0;
  for (int i = 0; i < n_in; ++i) {
    long s = in_sizes[i];
    if (s == (long)BB * TT * HH) {
      input = (const float*)d_in[i];
    } else if (s == BB * HH && !hidden) {
      hidden = (const float*)d_in[i];
    } else if (s == 3 * HH * HH) {
      if (!w_ih) w_ih = (const float*)d_in[i]; else w_hh = (const float*)d_in[i];
    } else if (s == 3 * HH) {
      if (!b_ih) b_ih = (const float*)d_in[i]; else b_hh = (const float*)d_in[i];
    }
  }
  gi_kernel<<<dim3(TT, 6), 256>>>(input, w_ih, b_ih);
  scan_kernel<<<NCTA, 256>>>(hidden, w_hh, b_hh, (float*)d_out);
}

// round 11
// speedup vs baseline: 4.0980x; 2.0971x over previous
#include <cuda_runtime.h>
#include <cstdint>
#include <cstddef>

#define TT 2048
#define BB 32
#define HH 256
#define NCELL (TT * 2)
#define NCTA 128          // 32 clusters x 4 CTAs, one batch per cluster

// ---------------- global scratch (allocation-free) ------------------------------
__device__ float g_gi[(size_t)TT * BB * 3 * HH];   // x @ w_ih^T + b_ih  [T][B][768]

// ---------------- helpers ---------------------------------------------------------
__device__ __forceinline__ uint32_t smem_u32(const void* p) {
  uint32_t a;
  asm("{ .reg .u64 t; cvta.to.shared.u64 t, %1; cvt.u32.u64 %0, t; }"
      : "=r"(a) : "l"(p));
  return a;
}
__device__ __forceinline__ uint64_t pack2(float a, float b) {
  uint64_t r;
  asm("mov.b64 %0, {%1, %2};" : "=l"(r) : "f"(a), "f"(b));
  return r;
}
__device__ __forceinline__ void unpack2(float& a, float& b, uint64_t v) {
  asm("mov.b64 {%0, %1}, %2;" : "=f"(a), "=f"(b) : "l"(v));
}
__device__ __forceinline__ void fma2(uint64_t& d, uint64_t a, uint64_t b) {
  asm("fma.rn.f32x2 %0, %1, %2, %0;" : "+l"(d) : "l"(a), "l"(b));
}
__device__ __forceinline__ float hadd(uint64_t v) {
  float a, b;
  unpack2(a, b, v);
  return a + b;
}
// store (value,seq) u64 into CTA `rank`'s SMEM at this CTA's local offset
__device__ __forceinline__ void st_cluster_u64(uint32_t local_addr, uint32_t rank,
                                               uint64_t v) {
  asm volatile(
      "{\n\t.reg .b32 ra;\n\t"
      "mapa.shared::cluster.u32 ra, %0, %1;\n\t"
      "st.relaxed.cluster.shared::cluster.u64 [ra], %2;\n\t}"
      :: "r"(local_addr), "r"(rank), "l"(v) : "memory");
}
__device__ __forceinline__ uint64_t ld_vol_u64(uint32_t addr) {
  uint64_t v;
  asm volatile("ld.volatile.shared.u64 %0, [%1];" : "=l"(v) : "r"(addr) : "memory");
  return v;
}
#define CLUSTER_SYNC_()                                              \
  do {                                                               \
    asm volatile("barrier.cluster.arrive.aligned;" ::: "memory");    \
    asm volatile("barrier.cluster.wait.aligned;" ::: "memory");      \
  } while (0)

// ---------------- gi precompute (f32x2 packed over k-pairs) -----------------------
__global__ __launch_bounds__(256) void gi_kernel(
    const float* __restrict__ x, const float* __restrict__ w_ih,
    const float* __restrict__ b_ih) {
  __shared__ float xs[32 * 260];
  __shared__ float ws[128 * 18];
  const int t   = blockIdx.x;
  const int gc0 = blockIdx.y * 128;
  const int tid = threadIdx.x;

  for (int i = tid; i < 2048; i += 256) {
    int b = i >> 6;
    int c4 = (i & 63) << 2;
    float4 v = *(const float4*)(x + ((size_t)b * TT + t) * HH + c4);
    *(float4*)(xs + b * 260 + c4) = v;
  }

  const int bq = tid >> 5;
  const int gq = tid & 31;

  uint64_t acc2[4][4];
#pragma unroll
  for (int i = 0; i < 4; i++)
#pragma unroll
    for (int j = 0; j < 4; j++) acc2[i][j] = pack2(0.f, 0.f);

  for (int kt = 0; kt < 16; ++kt) {
    const int k0 = kt * 16;
    __syncthreads();
    for (int i = tid; i < 1024; i += 256) {
      int r = i >> 3;
      int c2 = (i & 7) << 1;
      *(float2*)(ws + r * 18 + c2) =
          *(const float2*)(w_ih + (size_t)(gc0 + r) * HH + k0 + c2);
    }
    __syncthreads();
#pragma unroll
    for (int kp = 0; kp < 8; ++kp) {
      const int kk = kp << 1;
      uint64_t w2[4];
#pragma unroll
      for (int j = 0; j < 4; j++)
        w2[j] = *(const uint64_t*)(ws + (gq + 32 * j) * 18 + kk);
#pragma unroll
      for (int i = 0; i < 4; i++) {
        const uint64_t x2 = *(const uint64_t*)(xs + (bq * 4 + i) * 260 + k0 + kk);
#pragma unroll
        for (int j = 0; j < 4; j++) fma2(acc2[i][j], x2, w2[j]);
      }
    }
  }
#pragma unroll
  for (int j = 0; j < 4; j++) {
    int g = gc0 + gq + 32 * j;
    float bias = b_ih[g];
#pragma unroll
    for (int i = 0; i < 4; i++) {
      float a, b;
      unpack2(a, b, acc2[i][j]);
      g_gi[((size_t)t * BB + (bq * 4 + i)) * 768 + g] = a + b + bias;
    }
  }
}

// ---------------- clustered recurrent scan: 4 CTAs / 1 batch ----------------------
// CTA rank owns 64 h-cols (thread: 2 cols x 32-k slice; 96 u64 weight regs).
// Publish: 2 DSMEM (value,seq) u64 per lane (kq<4), rank=kq. Poll: 1 u64/thread.
__global__ __launch_bounds__(256, 1) __cluster_dims__(4, 1, 1)
void scan_kernel(const float* __restrict__ hidden, const float* __restrict__ w_hh,
                 const float* __restrict__ b_hh, float* __restrict__ out) {
  __shared__ __align__(16) unsigned long long bufs[2][HH];  // [parity][col]
  __shared__ __align__(16) float hT[8 * 34];                // padded k-slices

  const int tid  = threadIdx.x;
  const int rank = blockIdx.x & 3;
  const int b    = blockIdx.x >> 2;    // batch (0..31)
  const int warp = tid >> 5;
  const int lane = tid & 31;
  const int kq   = lane >> 2;          // K-slice [kq*32, kq*32+32); lane bits 2..4
  const int jl   = lane & 3;
  const int cp   = warp * 4 + jl;      // col pair 0..31
  const int col0 = rank * 64 + cp * 2; // global columns col0, col0+1

  // ---- persistent weights: 3 gates x 2 cols x 16 k-pairs = 96 u64 regs ----
  uint64_t w2[3][2][16];
#pragma unroll
  for (int g = 0; g < 3; ++g)
#pragma unroll
    for (int c = 0; c < 2; ++c) {
      const uint64_t* wp =
          (const uint64_t*)(w_hh + (size_t)(g * HH + col0 + c) * HH + kq * 32);
#pragma unroll
      for (int kp = 0; kp < 16; ++kp) w2[g][c][kp] = wp[kp];
    }
  float bias[3][2];
#pragma unroll
  for (int g = 0; g < 3; ++g)
#pragma unroll
    for (int c = 0; c < 2; ++c) bias[g][c] = b_hh[g * HH + col0 + c];

  // ---- init ----
  for (int i = tid; i < 2 * HH; i += 256) ((unsigned long long*)bufs)[i] = 0ull;
  for (int i = tid; i < HH; i += 256)
    hT[(i >> 5) * 34 + (i & 31)] = hidden[(size_t)b * HH + i];
  __syncthreads();
  CLUSTER_SYNC_();   // zeroed bufs visible before any peer publishes

  const uint32_t pollA = smem_u32(&bufs[0][0]) + (uint32_t)tid * 8u;
  const int hTpos = (tid >> 5) * 34 + (tid & 31);
  const int hold0 = ((col0) >> 5) * 34 + (col0 & 31);
  const int hold1 = ((col0 + 1) >> 5) * 34 + ((col0 + 1) & 31);

  for (int cell = 0; cell < NCELL; ++cell) {
    // ---- poll own SMEM (1 u64/thread), compact into padded hT ----
    if (cell > 0) {
      const uint32_t pa = pollA + (uint32_t)((cell & 1) ? HH * 8 : 0);
      const uint32_t tgt = (uint32_t)cell;
      uint64_t v = ld_vol_u64(pa);
      while ((uint32_t)(v >> 32) != tgt) {
        __nanosleep(20);
        v = ld_vol_u64(pa);
      }
      hT[hTpos] = __uint_as_float((uint32_t)v);
      __syncthreads();
    }
    // gi prefetch (L2/DRAM latency hidden behind FMA)
    const float* gp = g_gi + ((size_t)(cell >> 1) * BB + b) * 768 + col0;
    const float gir0 = __ldg(gp),       gir1 = __ldg(gp + 1);
    const float giz0 = __ldg(gp + 256), giz1 = __ldg(gp + 257);
    const float gin0 = __ldg(gp + 512), gin1 = __ldg(gp + 513);

    // ---- FMA: 96 fma2 (3 gates x 2 cols x 16 k-pairs), conflict-free LDS ----
    uint64_t aR0 = pack2(0.f, 0.f), aR1 = aR0, aZ0 = aR0, aZ1 = aR0,
             aN0 = aR0, aN1 = aR0;
    const uint64_t* H = (const uint64_t*)(&hT[kq * 34]);
#pragma unroll
    for (int kp = 0; kp < 16; ++kp) {
      const uint64_t h2 = H[kp];
      fma2(aR0, w2[0][0][kp], h2);
      fma2(aR1, w2[0][1][kp], h2);
      fma2(aZ0, w2[1][0][kp], h2);
      fma2(aZ1, w2[1][1][kp], h2);
      fma2(aN0, w2[2][0][kp], h2);
      fma2(aN1, w2[2][1][kp], h2);
    }
    float sR0 = hadd(aR0), sR1 = hadd(aR1), sZ0 = hadd(aZ0), sZ1 = hadd(aZ1),
          sN0 = hadd(aN0), sN1 = hadd(aN1);
    // butterfly over kq (lane bits 2..4): all lanes end with full dot products
#pragma unroll
    for (int m = 4; m <= 16; m <<= 1) {
      sR0 += __shfl_xor_sync(0xffffffffu, sR0, m);
      sR1 += __shfl_xor_sync(0xffffffffu, sR1, m);
      sZ0 += __shfl_xor_sync(0xffffffffu, sZ0, m);
      sZ1 += __shfl_xor_sync(0xffffffffu, sZ1, m);
      sN0 += __shfl_xor_sync(0xffffffffu, sN0, m);
      sN1 += __shfl_xor_sync(0xffffffffu, sN1, m);
    }

    // ---- gates (all lanes; redundant across kq) ----
    const float r0 = 1.f / (1.f + expf(-(gir0 + sR0 + bias[0][0])));
    const float z0 = 1.f / (1.f + expf(-(giz0 + sZ0 + bias[1][0])));
    const float n0 = tanhf(gin0 + r0 * (sN0 + bias[2][0]));
    const float hn0 = (1.f - z0) * n0 + z0 * hT[hold0];
    const float r1 = 1.f / (1.f + expf(-(gir1 + sR1 + bias[0][1])));
    const float z1 = 1.f / (1.f + expf(-(giz1 + sZ1 + bias[1][1])));
    const float n1 = tanhf(gin1 + r1 * (sN1 + bias[2][1]));
    const float hn1 = (1.f - z1) * n1 + z1 * hT[hold1];

    // ---- publish: lane kq<4 serves rank kq, 2 consecutive u64 ----
    if (cell + 1 < NCELL && kq < 4) {
      const uint64_t seqHi = (uint64_t)(uint32_t)(cell + 1) << 32;
      const uint32_t dst = smem_u32(&bufs[(cell + 1) & 1][col0]);
      st_cluster_u64(dst, (uint32_t)kq, seqHi | (uint64_t)__float_as_uint(hn0));
      st_cluster_u64(dst + 8u, (uint32_t)kq, seqHi | (uint64_t)__float_as_uint(hn1));
    }
    // ---- output (off critical path; dedicated lane group) ----
    if ((cell & 1) && kq == 4) {
      float* op = out + ((size_t)(cell >> 1) * BB + b) * HH + col0;
      op[0] = hn0;
      op[1] = hn1;
    }
  }
  CLUSTER_SYNC_();   // no CTA exits while peers may still store into its SMEM
}

// ---------------- launch ----------------------------------------------------------
extern "C" void kernel_launch(void* const* d_in, const int* in_sizes, int n_in,
                              void* d_out, int out_size) {
  const float *input = 0, *hidden = 0, *w_ih = 0, *w_hh = 0, *b_ih = 0, *b_hh = 0;
  for (int i = 0; i < n_in; ++i) {
    long s = in_sizes[i];
    if (s == (long)BB * TT * HH) {
      input = (const float*)d_in[i];
    } else if (s == BB * HH && !hidden) {
      hidden = (const float*)d_in[i];
    } else if (s == 3 * HH * HH) {
      if (!w_ih) w_ih = (const float*)d_in[i]; else w_hh = (const float*)d_in[i];
    } else if (s == 3 * HH) {
      if (!b_ih) b_ih = (const float*)d_in[i]; else b_hh = (const float*)d_in[i];
    }
  }
  gi_kernel<<<dim3(TT, 6), 256>>>(input, w_ih, b_ih);
  scan_kernel<<<NCTA, 256>>>(hidden, w_hh, b_hh, (float*)d_out);
}

// round 12
// speedup vs baseline: 4.8013x; 1.1716x over previous
#include <cuda_runtime.h>
#include <cstdint>
#include <cstddef>

#define TT 2048
#define BB 32
#define HH 256
#define NCELL (TT * 2)
#define NCTA 128          // 32 clusters x 4 CTAs, one batch per cluster

// ---------------- global scratch (allocation-free) ------------------------------
__device__ float g_gi[(size_t)TT * BB * 3 * HH];   // x @ w_ih^T + b_ih  [T][B][768]

// ---------------- helpers ---------------------------------------------------------
__device__ __forceinline__ uint32_t smem_u32(const void* p) {
  uint32_t a;
  asm("{ .reg .u64 t; cvta.to.shared.u64 t, %1; cvt.u32.u64 %0, t; }"
      : "=r"(a) : "l"(p));
  return a;
}
__device__ __forceinline__ uint64_t pack2(float a, float b) {
  uint64_t r;
  asm("mov.b64 %0, {%1, %2};" : "=l"(r) : "f"(a), "f"(b));
  return r;
}
__device__ __forceinline__ void unpack2(float& a, float& b, uint64_t v) {
  asm("mov.b64 {%0, %1}, %2;" : "=f"(a), "=f"(b) : "l"(v));
}
__device__ __forceinline__ void fma2(uint64_t& d, uint64_t a, uint64_t b) {
  asm("fma.rn.f32x2 %0, %1, %2, %0;" : "+l"(d) : "l"(a), "l"(b));
}
__device__ __forceinline__ float hadd(uint64_t v) {
  float a, b;
  unpack2(a, b, v);
  return a + b;
}
// fast gates: MUFU-based, ~1e-6 rel accuracy (threshold 1e-3; GRU is contractive)
__device__ __forceinline__ float fast_sigmoid(float x) {
  return 1.f / (1.f + __expf(-x));
}
__device__ __forceinline__ float fast_tanh(float x) {
  return 2.f / (1.f + __expf(-2.f * x)) - 1.f;
}
// store (value,seq) u64 into CTA `rank`'s SMEM at this CTA's local offset
__device__ __forceinline__ void st_cluster_u64(uint32_t local_addr, uint32_t rank,
                                               uint64_t v) {
  asm volatile(
      "{\n\t.reg .b32 ra;\n\t"
      "mapa.shared::cluster.u32 ra, %0, %1;\n\t"
      "st.relaxed.cluster.shared::cluster.u64 [ra], %2;\n\t}"
      :: "r"(local_addr), "r"(rank), "l"(v) : "memory");
}
__device__ __forceinline__ uint64_t ld_vol_u64(uint32_t addr) {
  uint64_t v;
  asm volatile("ld.volatile.shared.u64 %0, [%1];" : "=l"(v) : "r"(addr) : "memory");
  return v;
}
#define CLUSTER_SYNC_()                                              \
  do {                                                               \
    asm volatile("barrier.cluster.arrive.aligned;" ::: "memory");    \
    asm volatile("barrier.cluster.wait.aligned;" ::: "memory");      \
  } while (0)

// ---------------- gi precompute (f32x2 packed over k-pairs) -----------------------
__global__ __launch_bounds__(256) void gi_kernel(
    const float* __restrict__ x, const float* __restrict__ w_ih,
    const float* __restrict__ b_ih) {
  __shared__ float xs[32 * 260];
  __shared__ float ws[128 * 18];
  const int t   = blockIdx.x;
  const int gc0 = blockIdx.y * 128;
  const int tid = threadIdx.x;

  for (int i = tid; i < 2048; i += 256) {
    int b = i >> 6;
    int c4 = (i & 63) << 2;
    float4 v = *(const float4*)(x + ((size_t)b * TT + t) * HH + c4);
    *(float4*)(xs + b * 260 + c4) = v;
  }

  const int bq = tid >> 5;
  const int gq = tid & 31;

  uint64_t acc2[4][4];
#pragma unroll
  for (int i = 0; i < 4; i++)
#pragma unroll
    for (int j = 0; j < 4; j++) acc2[i][j] = pack2(0.f, 0.f);

  for (int kt = 0; kt < 16; ++kt) {
    const int k0 = kt * 16;
    __syncthreads();
    for (int i = tid; i < 1024; i += 256) {
      int r = i >> 3;
      int c2 = (i & 7) << 1;
      *(float2*)(ws + r * 18 + c2) =
          *(const float2*)(w_ih + (size_t)(gc0 + r) * HH + k0 + c2);
    }
    __syncthreads();
#pragma unroll
    for (int kp = 0; kp < 8; ++kp) {
      const int kk = kp << 1;
      uint64_t w2[4];
#pragma unroll
      for (int j = 0; j < 4; j++)
        w2[j] = *(const uint64_t*)(ws + (gq + 32 * j) * 18 + kk);
#pragma unroll
      for (int i = 0; i < 4; i++) {
        const uint64_t x2 = *(const uint64_t*)(xs + (bq * 4 + i) * 260 + k0 + kk);
#pragma unroll
        for (int j = 0; j < 4; j++) fma2(acc2[i][j], x2, w2[j]);
      }
    }
  }
#pragma unroll
  for (int j = 0; j < 4; j++) {
    int g = gc0 + gq + 32 * j;
    float bias = b_ih[g];
#pragma unroll
    for (int i = 0; i < 4; i++) {
      float a, b;
      unpack2(a, b, acc2[i][j]);
      g_gi[((size_t)t * BB + (bq * 4 + i)) * 768 + g] = a + b + bias;
    }
  }
}

// ---------------- clustered recurrent scan: 4 CTAs / 1 batch ----------------------
// Thread = (col, kq): 64 cols x 4 K-slices (kq = lane&3 -> 2-round butterfly).
// Weights: 3 gates x 32 k-pairs = 96 u64 regs. Publish: each thread exactly ONE
// DSMEM (value,seq) u64 to rank kq. Poll: 1 u64/thread on own SMEM.
__global__ __launch_bounds__(256, 1) __cluster_dims__(4, 1, 1)
void scan_kernel(const float* __restrict__ hidden, const float* __restrict__ w_hh,
                 const float* __restrict__ b_hh, float* __restrict__ out) {
  __shared__ __align__(16) unsigned long long bufs[2][HH];  // [parity][col]
  __shared__ __align__(16) float hT[4 * 66];                // padded 64-col slices

  const int tid  = threadIdx.x;
  const int rank = blockIdx.x & 3;
  const int b    = blockIdx.x >> 2;    // batch (0..31)
  const int warp = tid >> 5;
  const int lane = tid & 31;
  const int kq   = lane & 3;           // K-slice [kq*64, kq*64+64) floats
  const int colL = warp * 8 + (lane >> 2);   // 0..63
  const int col  = rank * 64 + colL;   // global column (this CTA's output col)

  // ---- persistent weights: 3 gates x 32 k-pairs = 96 u64 regs ----
  uint64_t w2[3][32];
#pragma unroll
  for (int g = 0; g < 3; ++g) {
    const uint64_t* wp =
        (const uint64_t*)(w_hh + (size_t)(g * HH + col) * HH + kq * 64);
#pragma unroll
    for (int kp = 0; kp < 32; ++kp) w2[g][kp] = wp[kp];
  }
  const float br = b_hh[0 * HH + col];
  const float bz = b_hh[1 * HH + col];
  const float bn = b_hh[2 * HH + col];

  // ---- init ----
  for (int i = tid; i < 2 * HH; i += 256) ((unsigned long long*)bufs)[i] = 0ull;
  for (int i = tid; i < HH; i += 256)
    hT[(i >> 6) * 66 + (i & 63)] = hidden[(size_t)b * HH + i];
  __syncthreads();
  CLUSTER_SYNC_();   // zeroed bufs visible before any peer publishes

  const uint32_t pollA = smem_u32(&bufs[0][0]) + (uint32_t)tid * 8u;
  const int hTpos = (tid >> 6) * 66 + (tid & 63);     // compact position (col=tid)
  const int holdP = (col >> 6) * 66 + (col & 63);     // own col position

  for (int cell = 0; cell < NCELL; ++cell) {
    // ---- poll own SMEM (1 u64/thread), compact into padded hT ----
    if (cell > 0) {
      const uint32_t pa = pollA + (uint32_t)((cell & 1) ? HH * 8 : 0);
      const uint32_t tgt = (uint32_t)cell;
      uint64_t v = ld_vol_u64(pa);
      while ((uint32_t)(v >> 32) != tgt) {
        __nanosleep(20);
        v = ld_vol_u64(pa);
      }
      hT[hTpos] = __uint_as_float((uint32_t)v);
      __syncthreads();
    }
    // gi prefetch (L2 latency hidden behind FMA)
    const float* gp = g_gi + ((size_t)(cell >> 1) * BB + b) * 768 + col;
    const float gir = __ldg(gp);
    const float giz = __ldg(gp + 256);
    const float gin = __ldg(gp + 512);

    // ---- FMA: 96 fma2 (3 gates x 32 k-pairs), conflict-free broadcast LDS ----
    uint64_t aR = pack2(0.f, 0.f), aZ = aR, aN = aR;
    const uint64_t* H = (const uint64_t*)(&hT[kq * 66]);
#pragma unroll
    for (int kp = 0; kp < 32; ++kp) {
      const uint64_t h2 = H[kp];
      fma2(aR, w2[0][kp], h2);
      fma2(aZ, w2[1][kp], h2);
      fma2(aN, w2[2][kp], h2);
    }
    float sR = hadd(aR), sZ = hadd(aZ), sN = hadd(aN);
    // butterfly over kq (lane bits 0..1): 2 rounds x 3 values
#pragma unroll
    for (int m = 1; m <= 2; m <<= 1) {
      sR += __shfl_xor_sync(0xffffffffu, sR, m);
      sZ += __shfl_xor_sync(0xffffffffu, sZ, m);
      sN += __shfl_xor_sync(0xffffffffu, sN, m);
    }

    // ---- gates (fast MUFU path), redundant across the 4 kq lanes of this col ----
    const float r = fast_sigmoid(gir + sR + br);
    const float z = fast_sigmoid(giz + sZ + bz);
    const float n = fast_tanh(gin + r * (sN + bn));
    const float hn = (1.f - z) * n + z * hT[holdP];

    // ---- publish FIRST (critical path): each thread -> rank kq, 1 u64 ----
    if (cell + 1 < NCELL) {
      const uint64_t pkd =
          ((uint64_t)(uint32_t)(cell + 1) << 32) | (uint64_t)__float_as_uint(hn);
      st_cluster_u64(smem_u32(&bufs[(cell + 1) & 1][col]), (uint32_t)kq, pkd);
    }
    // ---- output store (off critical path; one lane per col) ----
    if ((cell & 1) && kq == 3)
      out[((size_t)(cell >> 1) * BB + b) * HH + col] = hn;
  }
  CLUSTER_SYNC_();   // no CTA exits while peers may still store into its SMEM
}

// ---------------- launch ----------------------------------------------------------
extern "C" void kernel_launch(void* const* d_in, const int* in_sizes, int n_in,
                              void* d_out, int out_size) {
  const float *input = 0, *hidden = 0, *w_ih = 0, *w_hh = 0, *b_ih = 0, *b_hh = 0;
  for (int i = 0; i < n_in; ++i) {
    long s = in_sizes[i];
    if (s == (long)BB * TT * HH) {
      input = (const float*)d_in[i];
    } else if (s == BB * HH && !hidden) {
      hidden = (const float*)d_in[i];
    } else if (s == 3 * HH * HH) {
      if (!w_ih) w_ih = (const float*)d_in[i]; else w_hh = (const float*)d_in[i];
    } else if (s == 3 * HH) {
      if (!b_ih) b_ih = (const float*)d_in[i]; else b_hh = (const float*)d_in[i];
    }
  }
  gi_kernel<<<dim3(TT, 6), 256>>>(input, w_ih, b_ih);
  scan_kernel<<<NCTA, 256>>>(hidden, w_hh, b_hh, (float*)d_out);
}

// round 13
// speedup vs baseline: 5.4353x; 1.1321x over previous
#include <cuda_runtime.h>
#include <cstdint>
#include <cstddef>

#define TT 2048
#define BB 32
#define HH 256
#define NCELL (TT * 2)
#define NCTA 128          // 32 clusters x 4 CTAs, one batch per cluster

// ---------------- global scratch (allocation-free) ------------------------------
__device__ float g_gi[(size_t)TT * BB * 3 * HH];   // x @ w_ih^T + b_ih  [T][B][768]

// ---------------- helpers ---------------------------------------------------------
__device__ __forceinline__ uint32_t smem_u32(const void* p) {
  uint32_t a;
  asm("{ .reg .u64 t; cvta.to.shared.u64 t, %1; cvt.u32.u64 %0, t; }"
      : "=r"(a) : "l"(p));
  return a;
}
__device__ __forceinline__ uint64_t pack2(float a, float b) {
  uint64_t r;
  asm("mov.b64 %0, {%1, %2};" : "=l"(r) : "f"(a), "f"(b));
  return r;
}
__device__ __forceinline__ void unpack2(float& a, float& b, uint64_t v) {
  asm("mov.b64 {%0, %1}, %2;" : "=f"(a), "=f"(b) : "l"(v));
}
__device__ __forceinline__ void fma2(uint64_t& d, uint64_t a, uint64_t b) {
  asm("fma.rn.f32x2 %0, %1, %2, %0;" : "+l"(d) : "l"(a), "l"(b));
}
__device__ __forceinline__ float hadd(uint64_t v) {
  float a, b;
  unpack2(a, b, v);
  return a + b;
}
// fast gates: EX2 + fast reciprocal (MUFU), ~1e-6 rel accuracy
__device__ __forceinline__ float fast_sigmoid(float x) {
  return __fdividef(1.f, 1.f + __expf(-x));
}
__device__ __forceinline__ float fast_tanh(float x) {
  return __fdividef(2.f, 1.f + __expf(-2.f * x)) - 1.f;
}
// store (value,seq) u64 into CTA `rank`'s SMEM at this CTA's local offset
__device__ __forceinline__ void st_cluster_u64(uint32_t local_addr, uint32_t rank,
                                               uint64_t v) {
  asm volatile(
      "{\n\t.reg .b32 ra;\n\t"
      "mapa.shared::cluster.u32 ra, %0, %1;\n\t"
      "st.relaxed.cluster.shared::cluster.u64 [ra], %2;\n\t}"
      :: "r"(local_addr), "r"(rank), "l"(v) : "memory");
}
__device__ __forceinline__ uint64_t ld_vol_u64(uint32_t addr) {
  uint64_t v;
  asm volatile("ld.volatile.shared.u64 %0, [%1];" : "=l"(v) : "r"(addr) : "memory");
  return v;
}
#define CLUSTER_SYNC_()                                              \
  do {                                                               \
    asm volatile("barrier.cluster.arrive.aligned;" ::: "memory");    \
    asm volatile("barrier.cluster.wait.aligned;" ::: "memory");      \
  } while (0)

// ---------------- gi precompute (f32x2 packed over k-pairs) -----------------------
__global__ __launch_bounds__(256) void gi_kernel(
    const float* __restrict__ x, const float* __restrict__ w_ih,
    const float* __restrict__ b_ih) {
  __shared__ float xs[32 * 260];
  __shared__ float ws[128 * 18];
  const int t   = blockIdx.x;
  const int gc0 = blockIdx.y * 128;
  const int tid = threadIdx.x;

  for (int i = tid; i < 2048; i += 256) {
    int b = i >> 6;
    int c4 = (i & 63) << 2;
    float4 v = *(const float4*)(x + ((size_t)b * TT + t) * HH + c4);
    *(float4*)(xs + b * 260 + c4) = v;
  }

  const int bq = tid >> 5;
  const int gq = tid & 31;

  uint64_t acc2[4][4];
#pragma unroll
  for (int i = 0; i < 4; i++)
#pragma unroll
    for (int j = 0; j < 4; j++) acc2[i][j] = pack2(0.f, 0.f);

  for (int kt = 0; kt < 16; ++kt) {
    const int k0 = kt * 16;
    __syncthreads();
    for (int i = tid; i < 1024; i += 256) {
      int r = i >> 3;
      int c2 = (i & 7) << 1;
      *(float2*)(ws + r * 18 + c2) =
          *(const float2*)(w_ih + (size_t)(gc0 + r) * HH + k0 + c2);
    }
    __syncthreads();
#pragma unroll
    for (int kp = 0; kp < 8; ++kp) {
      const int kk = kp << 1;
      uint64_t w2[4];
#pragma unroll
      for (int j = 0; j < 4; j++)
        w2[j] = *(const uint64_t*)(ws + (gq + 32 * j) * 18 + kk);
#pragma unroll
      for (int i = 0; i < 4; i++) {
        const uint64_t x2 = *(const uint64_t*)(xs + (bq * 4 + i) * 260 + k0 + kk);
#pragma unroll
        for (int j = 0; j < 4; j++) fma2(acc2[i][j], x2, w2[j]);
      }
    }
  }
#pragma unroll
  for (int j = 0; j < 4; j++) {
    int g = gc0 + gq + 32 * j;
    float bias = b_ih[g];
#pragma unroll
    for (int i = 0; i < 4; i++) {
      float a, b;
      unpack2(a, b, acc2[i][j]);
      g_gi[((size_t)t * BB + (bq * 4 + i)) * 768 + g] = a + b + bias;
    }
  }
}

// ---------------- clustered recurrent scan: 4 CTAs / 1 batch ----------------------
// Thread = (col, kq): 64 cols x 4 K-slices (kq = lane&3 -> 2-round butterfly).
// Weights: 3 gates x 32 k-pairs = 96 u64 regs. Publish: each thread exactly ONE
// DSMEM (value,seq) u64 to rank kq. Poll: 1 u64/thread on own SMEM (tight spin).
// gi pipelined in registers, reloaded once per t (shared by both layer cells).
__global__ __launch_bounds__(256, 1) __cluster_dims__(4, 1, 1)
void scan_kernel(const float* __restrict__ hidden, const float* __restrict__ w_hh,
                 const float* __restrict__ b_hh, float* __restrict__ out) {
  __shared__ __align__(16) unsigned long long bufs[2][HH];  // [parity][col]
  __shared__ __align__(16) float hT[4 * 66];                // padded 64-col slices

  const int tid  = threadIdx.x;
  const int rank = blockIdx.x & 3;
  const int b    = blockIdx.x >> 2;    // batch (0..31)
  const int warp = tid >> 5;
  const int lane = tid & 31;
  const int kq   = lane & 3;           // K-slice [kq*64, kq*64+64) floats
  const int colL = warp * 8 + (lane >> 2);   // 0..63
  const int col  = rank * 64 + colL;   // global column (this CTA's output col)

  // ---- persistent weights: 3 gates x 32 k-pairs = 96 u64 regs ----
  uint64_t w2[3][32];
#pragma unroll
  for (int g = 0; g < 3; ++g) {
    const uint64_t* wp =
        (const uint64_t*)(w_hh + (size_t)(g * HH + col) * HH + kq * 64);
#pragma unroll
    for (int kp = 0; kp < 32; ++kp) w2[g][kp] = wp[kp];
  }
  const float br = b_hh[0 * HH + col];
  const float bz = b_hh[1 * HH + col];
  const float bn = b_hh[2 * HH + col];

  // ---- init ----
  for (int i = tid; i < 2 * HH; i += 256) ((unsigned long long*)bufs)[i] = 0ull;
  for (int i = tid; i < HH; i += 256)
    hT[(i >> 6) * 66 + (i & 63)] = hidden[(size_t)b * HH + i];
  __syncthreads();
  CLUSTER_SYNC_();   // zeroed bufs visible before any peer publishes

  const uint32_t pollBase = smem_u32(&bufs[0][0]) + (uint32_t)tid * 8u;
  const uint32_t dstA = smem_u32(&bufs[0][col]);       // parity-0 publish target
  const uint32_t dstB = dstA + (uint32_t)(HH * 8);     // parity-1 publish target
  const int hTpos = (tid >> 6) * 66 + (tid & 63);      // compact position (col=tid)
  const int holdP = (col >> 6) * 66 + (col & 63);      // own col position

  // gi registers for current t (shared by both layer cells of t)
  const float* gp0 = g_gi + (size_t)b * 768 + col;
  float gir = __ldg(gp0);
  float giz = __ldg(gp0 + 256);
  float gin = __ldg(gp0 + 512);

  for (int cell = 0; cell < NCELL; ++cell) {
    // ---- poll own SMEM (1 u64/thread, tight spin), compact into padded hT ----
    if (cell > 0) {
      const uint32_t pa = pollBase + (uint32_t)((cell & 1) ? HH * 8 : 0);
      const uint32_t tgt = (uint32_t)cell;
      uint64_t v = ld_vol_u64(pa);
      int spins = 0;
      while ((uint32_t)(v >> 32) != tgt) {
        if (++spins > 96) __nanosleep(20);
        v = ld_vol_u64(pa);
      }
      hT[hTpos] = __uint_as_float((uint32_t)v);
      __syncthreads();
    }

    // ---- FMA: 96 fma2 (3 gates x 32 k-pairs), conflict-free broadcast LDS ----
    const float hold = hT[holdP];
    uint64_t aR = pack2(0.f, 0.f), aZ = aR, aN = aR;
    const uint64_t* H = (const uint64_t*)(&hT[kq * 66]);
#pragma unroll
    for (int kp = 0; kp < 32; ++kp) {
      const uint64_t h2 = H[kp];
      fma2(aR, w2[0][kp], h2);
      fma2(aZ, w2[1][kp], h2);
      fma2(aN, w2[2][kp], h2);
    }
    float sR = hadd(aR), sZ = hadd(aZ), sN = hadd(aN);
    // butterfly over kq (lane bits 0..1): 2 rounds x 3 values
#pragma unroll
    for (int m = 1; m <= 2; m <<= 1) {
      sR += __shfl_xor_sync(0xffffffffu, sR, m);
      sZ += __shfl_xor_sync(0xffffffffu, sZ, m);
      sN += __shfl_xor_sync(0xffffffffu, sN, m);
    }

    // ---- gates (MUFU EX2 + fast reciprocal), redundant across kq lanes ----
    const float r = fast_sigmoid(gir + sR + br);
    const float z = fast_sigmoid(giz + sZ + bz);
    const float n = fast_tanh(gin + r * (sN + bn));
    const float hn = (1.f - z) * n + z * hold;

    // ---- publish FIRST (critical path): each thread -> rank kq, 1 u64 ----
    if (cell + 1 < NCELL) {
      const uint64_t pkd =
          ((uint64_t)(uint32_t)(cell + 1) << 32) | (uint64_t)__float_as_uint(hn);
      st_cluster_u64(((cell + 1) & 1) ? dstB : dstA, (uint32_t)kq, pkd);
    }
    // ---- off critical path: output store + gi prefetch for next t ----
    if (cell & 1) {
      if (kq == 3)
        out[((size_t)(cell >> 1) * BB + b) * HH + col] = hn;
      if (cell + 1 < NCELL) {   // next cell starts a new t: reload gi (hidden)
        const float* gp =
            g_gi + ((size_t)((cell + 1) >> 1) * BB + b) * 768 + col;
        gir = __ldg(gp);
        giz = __ldg(gp + 256);
        gin = __ldg(gp + 512);
      }
    }
  }
  CLUSTER_SYNC_();   // no CTA exits while peers may still store into its SMEM
}

// ---------------- launch ----------------------------------------------------------
extern "C" void kernel_launch(void* const* d_in, const int* in_sizes, int n_in,
                              void* d_out, int out_size) {
  const float *input = 0, *hidden = 0, *w_ih = 0, *w_hh = 0, *b_ih = 0, *b_hh = 0;
  for (int i = 0; i < n_in; ++i) {
    long s = in_sizes[i];
    if (s == (long)BB * TT * HH) {
      input = (const float*)d_in[i];
    } else if (s == BB * HH && !hidden) {
      hidden = (const float*)d_in[i];
    } else if (s == 3 * HH * HH) {
      if (!w_ih) w_ih = (const float*)d_in[i]; else w_hh = (const float*)d_in[i];
    } else if (s == 3 * HH) {
      if (!b_ih) b_ih = (const float*)d_in[i]; else b_hh = (const float*)d_in[i];
    }
  }
  gi_kernel<<<dim3(TT, 6), 256>>>(input, w_ih, b_ih);
  scan_kernel<<<NCTA, 256>>>(hidden, w_hh, b_hh, (float*)d_out);
}